// round 2
// baseline (speedup 1.0000x reference)
#include <cuda_runtime.h>
#include <cstdint>

#define Bb 2
#define Nn 2048
#define Hh 8
#define DHd 64
#define Kk 32
#define SCALEf 0.125f
#define NEG_HUGE (-3.402823466e+38f)

typedef unsigned long long u64;

// ---------------- packed f32x2 helpers (B300 FFMA2 path) ----------------
__device__ __forceinline__ u64 pack2(float x, float y) {
    u64 r; asm("mov.b64 %0, {%1, %2};" : "=l"(r) : "f"(x), "f"(y)); return r;
}
__device__ __forceinline__ void unpack2(u64 v, float& x, float& y) {
    asm("mov.b64 {%0, %1}, %2;" : "=f"(x), "=f"(y) : "l"(v));
}
__device__ __forceinline__ void ffma2(u64& d, u64 a, u64 b) {
    asm("fma.rn.f32x2 %0, %1, %2, %0;" : "+l"(d) : "l"(a), "l"(b));
}
__device__ __forceinline__ u64 fmul2(u64 a, u64 b) {
    u64 r; asm("mul.rn.f32x2 %0, %1, %2;" : "=l"(r) : "l"(a), "l"(b)); return r;
}

// ---------------- scratch ----------------
__device__ float g_q[Bb * Nn * (Hh * DHd)];
__device__ float g_kv[Bb * Nn * (2 * DHd)];
__device__ float g_local[Bb * Hh * Nn * DHd];
__device__ float g_comb[Bb * Nn * (Hh * DHd)];
__device__ unsigned char g_mask[Bb * Hh * Nn * Kk];
__device__ int g_mask_mode;

// ---------------- mask dtype detection / expansion ----------------
__global__ void detect_mask_kernel(const unsigned int* __restrict__ raw) {
    __shared__ int cf, ch;
    if (threadIdx.x == 0) { cf = 0; ch = 0; }
    __syncthreads();
    int lf = 0, lh = 0;
    for (int idx = threadIdx.x; idx < 4096; idx += 256) {
        unsigned w = raw[idx];
        if (w == 0x3f800000u) lf++;
        if (w & 0xFFFFFF00u) lh++;
    }
    atomicAdd(&cf, lf);
    atomicAdd(&ch, lh);
    __syncthreads();
    if (threadIdx.x == 0) {
        int mode;
        if (cf > 64) mode = 2;
        else if (ch > 64) mode = 0;
        else mode = 1;
        g_mask_mode = mode;
    }
}

__global__ void expand_mask_kernel(const void* __restrict__ raw, int n) {
    int idx = blockIdx.x * blockDim.x + threadIdx.x;
    if (idx >= n) return;
    int mode = g_mask_mode;
    unsigned char v;
    if (mode == 0)      v = ((const unsigned char*)raw)[idx] != 0;
    else if (mode == 1) v = ((const int*)raw)[idx] != 0;
    else                v = (((const float*)raw)[idx] != 0.0f);
    g_mask[idx] = v;
}

// ---------------- FFMA2 GEMM: 128x64 tile, BK=16, 128 threads, 8x8 micro ----------------
// Dual-B: blocks with blockIdx.x < nb1 use (B1,C1), rest use (B2,C2).
__global__ void __launch_bounds__(128) gemm_kernel(
    const float* __restrict__ A,
    const float* __restrict__ B1, float* __restrict__ C1, int ldb1, int ldc1,
    const float* __restrict__ B2, float* __restrict__ C2, int ldb2, int ldc2,
    int nb1, const float* __restrict__ bias, int Kd)
{
    __shared__ float Ast[16 * 132];  // [k][r], stride 132
    __shared__ float Bs[16 * 64];    // [k][c]
    int tid = threadIdx.x;
    int tx = tid & 7, ty = tid >> 3;
    int rowBase = blockIdx.y * 128;
    const float* Bm; float* C; int ldb, ldc, colBase;
    if ((int)blockIdx.x < nb1) {
        Bm = B1; C = C1; ldb = ldb1; ldc = ldc1; colBase = blockIdx.x * 64;
    } else {
        Bm = B2; C = C2; ldb = ldb2; ldc = ldc2; colBase = (blockIdx.x - nb1) * 64;
    }

    u64 acc[8][4];
#pragma unroll
    for (int i = 0; i < 8; i++)
#pragma unroll
        for (int j = 0; j < 4; j++) acc[i][j] = 0ull;

    int arow = tid >> 2;
    int akq = (tid & 3) * 4;
    int bkr = tid >> 4;
    int bc4 = (tid & 15) * 4;

    for (int k0 = 0; k0 < Kd; k0 += 16) {
#pragma unroll
        for (int rep = 0; rep < 4; rep++) {
            int r = arow + rep * 32;
            float4 v = *(const float4*)&A[(size_t)(rowBase + r) * Kd + k0 + akq];
            Ast[(akq + 0) * 132 + r] = v.x;
            Ast[(akq + 1) * 132 + r] = v.y;
            Ast[(akq + 2) * 132 + r] = v.z;
            Ast[(akq + 3) * 132 + r] = v.w;
        }
#pragma unroll
        for (int rep = 0; rep < 2; rep++) {
            int kk = bkr + rep * 8;
            *(float4*)&Bs[kk * 64 + bc4] =
                *(const float4*)&Bm[(size_t)(k0 + kk) * ldb + colBase + bc4];
        }
        __syncthreads();
#pragma unroll 8
        for (int kk = 0; kk < 16; kk++) {
            float4 a0 = *(const float4*)&Ast[kk * 132 + ty * 8];
            float4 a1 = *(const float4*)&Ast[kk * 132 + ty * 8 + 4];
            ulonglong2 b01 = *(const ulonglong2*)&Bs[kk * 64 + tx * 8];
            ulonglong2 b23 = *(const ulonglong2*)&Bs[kk * 64 + tx * 8 + 4];
            u64 aa[8];
            aa[0] = pack2(a0.x, a0.x); aa[1] = pack2(a0.y, a0.y);
            aa[2] = pack2(a0.z, a0.z); aa[3] = pack2(a0.w, a0.w);
            aa[4] = pack2(a1.x, a1.x); aa[5] = pack2(a1.y, a1.y);
            aa[6] = pack2(a1.z, a1.z); aa[7] = pack2(a1.w, a1.w);
            u64 bb[4] = {b01.x, b01.y, b23.x, b23.y};
#pragma unroll
            for (int i = 0; i < 8; i++)
#pragma unroll
                for (int j = 0; j < 4; j++) ffma2(acc[i][j], aa[i], bb[j]);
        }
        __syncthreads();
    }

    float bv[8];
#pragma unroll
    for (int j = 0; j < 8; j++) bv[j] = 0.f;
    if (bias) {
#pragma unroll
        for (int j = 0; j < 8; j++) bv[j] = bias[colBase + tx * 8 + j];
    }
#pragma unroll
    for (int i = 0; i < 8; i++) {
        float o[8];
        unpack2(acc[i][0], o[0], o[1]);
        unpack2(acc[i][1], o[2], o[3]);
        unpack2(acc[i][2], o[4], o[5]);
        unpack2(acc[i][3], o[6], o[7]);
        size_t off = (size_t)(rowBase + ty * 8 + i) * ldc + colBase + tx * 8;
        float4 w0 = {o[0] + bv[0], o[1] + bv[1], o[2] + bv[2], o[3] + bv[3]};
        float4 w1 = {o[4] + bv[4], o[5] + bv[5], o[6] + bv[6], o[7] + bv[7]};
        *(float4*)&C[off] = w0;
        *(float4*)&C[off + 4] = w1;
    }
}

// ---------------- FFMA2 flash attention: Q tile 128, K/V tile 64, 128 threads ----------------
__global__ void __launch_bounds__(128) flash_kernel(
    const float* __restrict__ q, const float* __restrict__ kv,
    float* __restrict__ localOut)
{
    extern __shared__ float sm[];
    float* Qt = sm;                // [64][128]  Qt[d][r]
    float* Kt = sm + 64 * 128;     // [64][64]   Kt[d][c]
    float* Vs = Kt + 64 * 64;      // [64][64]   Vs[c][d]
    float* Pt = Vs + 64 * 64;      // [64][128]  Pt[c][r], r XOR-swizzled by (c>>3)

    int tid = threadIdx.x;
    int tx = tid & 7, ty = tid >> 3;
    int bh = blockIdx.y, b = bh >> 3, h = bh & 7;
    // pair-balanced qb ordering: (bx, bx+4) pairs sum to equal work
    const int perm[16] = {15, 7, 11, 3, 0, 8, 4, 12, 14, 6, 10, 2, 1, 9, 5, 13};
    int qb = perm[blockIdx.x];
    int i0 = qb * 128;

    // load Q transposed: lanes vary r (conflict-free STS)
    {
        int r0 = tid & 31;
        int d4 = 4 * (tid >> 5);
#pragma unroll
        for (int rep = 0; rep < 16; rep++) {
            int r = r0 + 32 * (rep & 3);
            int d = d4 + 16 * (rep >> 2);
            float4 v = *(const float4*)&q[(size_t)(b * Nn + i0 + r) * 512 + h * 64 + d];
            Qt[(d + 0) * 128 + r] = v.x;
            Qt[(d + 1) * 128 + r] = v.y;
            Qt[(d + 2) * 128 + r] = v.z;
            Qt[(d + 3) * 128 + r] = v.w;
        }
    }

    u64 oacc[8][4];
#pragma unroll
    for (int i = 0; i < 8; i++)
#pragma unroll
        for (int j = 0; j < 4; j++) oacc[i][j] = 0ull;
    float m_i[8], l_i[8];
#pragma unroll
    for (int i = 0; i < 8; i++) { m_i[i] = NEG_HUGE; l_i[i] = 0.f; }
    __syncthreads();

    int numJ = 2 * qb + 2;
    for (int jb = 0; jb < numJ; jb++) {
        int j0 = jb * 64;
        // K transposed (lanes vary c) + V natural
        {
            int c0 = tid & 31;
            int d4 = 4 * (tid >> 5);
#pragma unroll
            for (int rep = 0; rep < 8; rep++) {
                int c = c0 + 32 * (rep & 1);
                int d = d4 + 16 * (rep >> 1);
                float4 v = *(const float4*)&kv[(size_t)(b * Nn + j0 + c) * 128 + d];
                Kt[(d + 0) * 64 + c] = v.x;
                Kt[(d + 1) * 64 + c] = v.y;
                Kt[(d + 2) * 64 + c] = v.z;
                Kt[(d + 3) * 64 + c] = v.w;
            }
#pragma unroll
            for (int rep = 0; rep < 8; rep++) {
                int e = tid + rep * 128;
                int c = e >> 4, dd = (e & 15) * 4;
                *(float4*)&Vs[c * 64 + dd] =
                    *(const float4*)&kv[(size_t)(b * Nn + j0 + c) * 128 + 64 + dd];
            }
        }
        __syncthreads();

        // S = Q @ K^T (col-pair packed accumulators)
        u64 sacc[8][4];
#pragma unroll
        for (int i = 0; i < 8; i++)
#pragma unroll
            for (int j = 0; j < 4; j++) sacc[i][j] = 0ull;
#pragma unroll 4
        for (int d = 0; d < 64; d++) {
            float4 a0 = *(const float4*)&Qt[d * 128 + ty * 8];
            float4 a1 = *(const float4*)&Qt[d * 128 + ty * 8 + 4];
            ulonglong2 b01 = *(const ulonglong2*)&Kt[d * 64 + tx * 8];
            ulonglong2 b23 = *(const ulonglong2*)&Kt[d * 64 + tx * 8 + 4];
            u64 aa[8];
            aa[0] = pack2(a0.x, a0.x); aa[1] = pack2(a0.y, a0.y);
            aa[2] = pack2(a0.z, a0.z); aa[3] = pack2(a0.w, a0.w);
            aa[4] = pack2(a1.x, a1.x); aa[5] = pack2(a1.y, a1.y);
            aa[6] = pack2(a1.z, a1.z); aa[7] = pack2(a1.w, a1.w);
            u64 bb[4] = {b01.x, b01.y, b23.x, b23.y};
#pragma unroll
            for (int i = 0; i < 8; i++)
#pragma unroll
                for (int j = 0; j < 4; j++) ffma2(sacc[i][j], aa[i], bb[j]);
        }

        // online softmax per row; write P row immediately (keeps reg pressure low)
        bool diag = (j0 + 63 > i0);
#pragma unroll
        for (int i = 0; i < 8; i++) {
            float s[8];
            unpack2(sacc[i][0], s[0], s[1]);
            unpack2(sacc[i][1], s[2], s[3]);
            unpack2(sacc[i][2], s[4], s[5]);
            unpack2(sacc[i][3], s[6], s[7]);
            int ri = i0 + ty * 8 + i;
            if (diag) {
#pragma unroll
                for (int j = 0; j < 8; j++)
                    if (j0 + tx * 8 + j > ri) s[j] = NEG_HUGE;
            }
            float mx = s[0];
#pragma unroll
            for (int j = 1; j < 8; j++) mx = fmaxf(mx, s[j]);
            mx = fmaxf(mx, __shfl_xor_sync(0xffffffffu, mx, 1));
            mx = fmaxf(mx, __shfl_xor_sync(0xffffffffu, mx, 2));
            mx = fmaxf(mx, __shfl_xor_sync(0xffffffffu, mx, 4));
            float nm = fmaxf(m_i[i], mx);
            float alpha = __expf((m_i[i] - nm) * SCALEf);
            m_i[i] = nm;
            float rs = 0.f;
            float p[8];
#pragma unroll
            for (int j = 0; j < 8; j++) { p[j] = __expf((s[j] - nm) * SCALEf); rs += p[j]; }
            rs += __shfl_xor_sync(0xffffffffu, rs, 1);
            rs += __shfl_xor_sync(0xffffffffu, rs, 2);
            rs += __shfl_xor_sync(0xffffffffu, rs, 4);
            l_i[i] = l_i[i] * alpha + rs;
            u64 al2 = pack2(alpha, alpha);
#pragma unroll
            for (int jp = 0; jp < 4; jp++) oacc[i][jp] = fmul2(oacc[i][jp], al2);
            int rphys = (ty * 8 + i) ^ (8 * tx);   // swizzle by c>>3 == tx
#pragma unroll
            for (int j = 0; j < 8; j++)
                Pt[(tx * 8 + j) * 128 + rphys] = p[j];
        }
        __syncthreads();

        // O += P @ V (d-pair packed accumulators)
#pragma unroll 4
        for (int c = 0; c < 64; c++) {
            int rsw = (ty * 8) ^ (8 * (c >> 3));
            float4 a0 = *(const float4*)&Pt[c * 128 + rsw];
            float4 a1 = *(const float4*)&Pt[c * 128 + rsw + 4];
            ulonglong2 b01 = *(const ulonglong2*)&Vs[c * 64 + tx * 8];
            ulonglong2 b23 = *(const ulonglong2*)&Vs[c * 64 + tx * 8 + 4];
            u64 aa[8];
            aa[0] = pack2(a0.x, a0.x); aa[1] = pack2(a0.y, a0.y);
            aa[2] = pack2(a0.z, a0.z); aa[3] = pack2(a0.w, a0.w);
            aa[4] = pack2(a1.x, a1.x); aa[5] = pack2(a1.y, a1.y);
            aa[6] = pack2(a1.z, a1.z); aa[7] = pack2(a1.w, a1.w);
            u64 bb[4] = {b01.x, b01.y, b23.x, b23.y};
#pragma unroll
            for (int i = 0; i < 8; i++)
#pragma unroll
                for (int j = 0; j < 4; j++) ffma2(oacc[i][j], aa[i], bb[j]);
        }
        __syncthreads();
    }

#pragma unroll
    for (int i = 0; i < 8; i++) {
        float inv = 1.f / l_i[i];
        float o[8];
        unpack2(oacc[i][0], o[0], o[1]);
        unpack2(oacc[i][1], o[2], o[3]);
        unpack2(oacc[i][2], o[4], o[5]);
        unpack2(oacc[i][3], o[6], o[7]);
        size_t off = ((size_t)bh * Nn + i0 + ty * 8 + i) * 64 + tx * 8;
        float4 w0 = {o[0] * inv, o[1] * inv, o[2] * inv, o[3] * inv};
        float4 w1 = {o[4] * inv, o[5] * inv, o[6] * inv, o[7] * inv};
        *(float4*)&localOut[off] = w0;
        *(float4*)&localOut[off + 4] = w1;
    }
}

// ---------------- memory (KNN) attention + gate combine ----------------
__global__ void mem_attn_kernel(const float* __restrict__ q,
                                const float* __restrict__ memkv,
                                const float* __restrict__ nullk,
                                const float* __restrict__ nullv,
                                const float* __restrict__ gate,
                                const float* __restrict__ localv,
                                float* __restrict__ comb) {
    int gw = blockIdx.x * 8 + (threadIdx.x >> 5);
    int lane = threadIdx.x & 31;
    int b = gw >> 14;
    int rem = gw & 16383;
    int h = rem >> 11;
    int i = rem & 2047;

    const float* qp = &q[(size_t)(b * Nn + i) * 512 + h * 64];
    float q0 = qp[lane], q1 = qp[lane + 32];

    float s = q0 * nullk[lane] + q1 * nullk[lane + 32];
#pragma unroll
    for (int off = 16; off >= 1; off >>= 1) s += __shfl_xor_sync(0xffffffffu, s, off);
    s *= SCALEf;
    float m = s, ls = 1.f;
    float a0 = nullv[lane], a1 = nullv[lane + 32];

    size_t base = (size_t)(b * Hh + h) * Nn + i;
    const unsigned char* mp = &g_mask[base * Kk];
    unsigned mbits = __ballot_sync(0xffffffffu, mp[lane] != 0);
    const float* kvp = &memkv[base * (size_t)(Kk * 2 * DHd)];

    for (int kk = 0; kk < Kk; kk++) {
        if (!((mbits >> kk) & 1u)) continue;
        const float* kp = kvp + (size_t)kk * 128;
        float ss = q0 * kp[lane] + q1 * kp[lane + 32];
#pragma unroll
        for (int off = 16; off >= 1; off >>= 1) ss += __shfl_xor_sync(0xffffffffu, ss, off);
        ss *= SCALEf;
        float nm = fmaxf(m, ss);
        float al = __expf(m - nm);
        float p = __expf(ss - nm);
        m = nm;
        ls = ls * al + p;
        a0 = a0 * al + p * kp[64 + lane];
        a1 = a1 * al + p * kp[96 + lane];
    }
    float inv = 1.f / ls;
    float mem0 = a0 * inv, mem1 = a1 * inv;

    float g = 1.f / (1.f + __expf(-gate[h]));
    const float* lp = &localv[base * DHd];
    float* cp = &comb[(size_t)(b * Nn + i) * 512 + h * 64];
    cp[lane]      = lp[lane]      * g + mem0 * (1.f - g);
    cp[lane + 32] = lp[lane + 32] * g + mem1 * (1.f - g);
}

// ---------------- launch ----------------
extern "C" void kernel_launch(void* const* d_in, const int* in_sizes, int n_in,
                              void* d_out, int out_size) {
    const float* x      = (const float*)d_in[0];
    const float* mem_kv = (const float*)d_in[1];
    const void*  m_mask = d_in[2];
    const float* Wq     = (const float*)d_in[3];
    const float* Wkv    = (const float*)d_in[4];
    const float* Wo     = (const float*)d_in[5];
    const float* bo     = (const float*)d_in[6];
    const float* null_k = (const float*)d_in[7];
    const float* null_v = (const float*)d_in[8];
    const float* gate   = (const float*)d_in[9];
    float* out = (float*)d_out;

    float* q_buf;     cudaGetSymbolAddress((void**)&q_buf, g_q);
    float* kv_buf;    cudaGetSymbolAddress((void**)&kv_buf, g_kv);
    float* local_buf; cudaGetSymbolAddress((void**)&local_buf, g_local);
    float* comb_buf;  cudaGetSymbolAddress((void**)&comb_buf, g_comb);

    cudaFuncSetAttribute(flash_kernel, cudaFuncAttributeMaxDynamicSharedMemorySize,
                         96 * 1024);

    detect_mask_kernel<<<1, 256>>>((const unsigned int*)m_mask);
    expand_mask_kernel<<<(Bb * Hh * Nn * Kk + 255) / 256, 256>>>(m_mask,
                                                                 Bb * Hh * Nn * Kk);

    // fused q + kv projection: cols 0..511 -> Wq/g_q, 512..639 -> Wkv/g_kv
    gemm_kernel<<<dim3(10, (Bb * Nn) / 128), 128>>>(
        x, Wq, q_buf, 512, 512, Wkv, kv_buf, 128, 128, 8, nullptr, 512);

    // local causal flash attention
    flash_kernel<<<dim3(16, Bb * Hh), 128, 96 * 1024>>>(q_buf, kv_buf, local_buf);

    // memory attention + gate combine
    mem_attn_kernel<<<(Bb * Hh * Nn) / 8, 256>>>(q_buf, mem_kv, null_k, null_v,
                                                 gate, local_buf, comb_buf);

    // output projection with bias
    gemm_kernel<<<dim3(8, (Bb * Nn) / 128), 128>>>(
        comb_buf, Wo, out, 512, 512, Wo, out, 512, 512, 8, bo, 512);
}

// round 3
// speedup vs baseline: 2.5714x; 2.5714x over previous
#include <cuda_runtime.h>
#include <cstdint>

#define Bb 2
#define Nn 2048
#define Hh 8
#define DHd 64
#define Kk 32
#define SCALEf 0.125f
#define NEG_HUGE (-3.402823466e+38f)

// ---------------- tf32 helpers ----------------
__device__ __forceinline__ unsigned f2tf(float x) {
    unsigned r; asm("cvt.rna.tf32.f32 %0, %1;" : "=r"(r) : "f"(x)); return r;
}
__device__ __forceinline__ void mma_tf32(float* d, const unsigned* a, const unsigned* b) {
    asm volatile(
        "mma.sync.aligned.m16n8k8.row.col.f32.tf32.tf32.f32 "
        "{%0,%1,%2,%3}, {%4,%5,%6,%7}, {%8,%9}, {%0,%1,%2,%3};\n"
        : "+f"(d[0]), "+f"(d[1]), "+f"(d[2]), "+f"(d[3])
        : "r"(a[0]), "r"(a[1]), "r"(a[2]), "r"(a[3]), "r"(b[0]), "r"(b[1]));
}

// ---------------- scratch ----------------
__device__ float g_q[Bb * Nn * (Hh * DHd)];
__device__ float g_kv[Bb * Nn * (2 * DHd)];
__device__ float g_local[Bb * Hh * Nn * DHd];
__device__ float g_comb[Bb * Nn * (Hh * DHd)];
__device__ unsigned char g_mask[Bb * Hh * Nn * Kk];
__device__ int g_mask_mode;

// ---------------- mask dtype detection / expansion ----------------
__global__ void detect_mask_kernel(const unsigned int* __restrict__ raw) {
    __shared__ int cf, ch;
    if (threadIdx.x == 0) { cf = 0; ch = 0; }
    __syncthreads();
    int lf = 0, lh = 0;
    for (int idx = threadIdx.x; idx < 4096; idx += 256) {
        unsigned w = raw[idx];
        if (w == 0x3f800000u) lf++;
        if (w & 0xFFFFFF00u) lh++;
    }
    atomicAdd(&cf, lf);
    atomicAdd(&ch, lh);
    __syncthreads();
    if (threadIdx.x == 0) {
        int mode;
        if (cf > 64) mode = 2;
        else if (ch > 64) mode = 0;
        else mode = 1;
        g_mask_mode = mode;
    }
}

__global__ void expand_mask_kernel(const void* __restrict__ raw, int n) {
    int idx = blockIdx.x * blockDim.x + threadIdx.x;
    if (idx >= n) return;
    int mode = g_mask_mode;
    unsigned char v;
    if (mode == 0)      v = ((const unsigned char*)raw)[idx] != 0;
    else if (mode == 1) v = ((const int*)raw)[idx] != 0;
    else                v = (((const float*)raw)[idx] != 0.0f);
    g_mask[idx] = v;
}

// ---------------- tf32 MMA GEMM: tile 128x64, BK=32, 256 threads (8 warps) ----------------
// Warp w owns rows w*16..w*16+15 of the tile, all 64 cols.
// Dual-B: blockIdx.x < nb1 -> (B1,C1) else (B2,C2).
__global__ void __launch_bounds__(256) gemm_kernel(
    const float* __restrict__ A,
    const float* __restrict__ B1, float* __restrict__ C1, int ldb1, int ldc1,
    const float* __restrict__ B2, float* __restrict__ C2, int ldb2, int ldc2,
    int nb1, const float* __restrict__ bias, int Kd)
{
    __shared__ unsigned As[128 * 36];  // [r][k] pad 36
    __shared__ unsigned Bs[32 * 68];   // [k][n] pad 68
    int tid = threadIdx.x;
    int warp = tid >> 5, lane = tid & 31;
    int lg = lane >> 2, lt = lane & 3;     // group id, thread-in-group
    int rowBase = blockIdx.y * 128;
    const float* Bm; float* C; int ldb, ldc, colBase;
    bool hasBias;
    if ((int)blockIdx.x < nb1) {
        Bm = B1; C = C1; ldb = ldb1; ldc = ldc1; colBase = blockIdx.x * 64;
        hasBias = false;
    } else {
        Bm = B2; C = C2; ldb = ldb2; ldc = ldc2; colBase = (blockIdx.x - nb1) * 64;
        hasBias = (bias != nullptr);
    }

    float acc[8][4];
#pragma unroll
    for (int j = 0; j < 8; j++)
#pragma unroll
        for (int q = 0; q < 4; q++) acc[j][q] = 0.f;

    int r0 = warp * 16;

    for (int k0 = 0; k0 < Kd; k0 += 32) {
        // stage A 128x32 (tf32)
#pragma unroll
        for (int rep = 0; rep < 4; rep++) {
            int r = (tid >> 3) + rep * 32;
            int kq = (tid & 7) * 4;
            float4 v = *(const float4*)&A[(size_t)(rowBase + r) * Kd + k0 + kq];
            uint4 u = {f2tf(v.x), f2tf(v.y), f2tf(v.z), f2tf(v.w)};
            *(uint4*)&As[r * 36 + kq] = u;
        }
        // stage B 32x64 (tf32)
#pragma unroll
        for (int rep = 0; rep < 2; rep++) {
            int kk = (tid >> 4) + rep * 16;
            int c4 = (tid & 15) * 4;
            float4 v = *(const float4*)&Bm[(size_t)(k0 + kk) * ldb + colBase + c4];
            uint4 u = {f2tf(v.x), f2tf(v.y), f2tf(v.z), f2tf(v.w)};
            *(uint4*)&Bs[kk * 68 + c4] = u;
        }
        __syncthreads();
#pragma unroll
        for (int kc = 0; kc < 4; kc++) {
            unsigned a[4];
            a[0] = As[(r0 + lg) * 36 + kc * 8 + lt];
            a[1] = As[(r0 + lg + 8) * 36 + kc * 8 + lt];
            a[2] = As[(r0 + lg) * 36 + kc * 8 + lt + 4];
            a[3] = As[(r0 + lg + 8) * 36 + kc * 8 + lt + 4];
#pragma unroll
            for (int jn = 0; jn < 8; jn++) {
                unsigned bfr[2];
                bfr[0] = Bs[(kc * 8 + lt) * 68 + jn * 8 + lg];
                bfr[1] = Bs[(kc * 8 + lt + 4) * 68 + jn * 8 + lg];
                mma_tf32(acc[jn], a, bfr);
            }
        }
        __syncthreads();
    }

#pragma unroll
    for (int jn = 0; jn < 8; jn++) {
        int col = colBase + jn * 8 + 2 * lt;
        float b0 = 0.f, b1 = 0.f;
        if (hasBias) { b0 = bias[col]; b1 = bias[col + 1]; }
        float2 w0 = {acc[jn][0] + b0, acc[jn][1] + b1};
        float2 w1 = {acc[jn][2] + b0, acc[jn][3] + b1};
        *(float2*)&C[(size_t)(rowBase + r0 + lg) * ldc + col] = w0;
        *(float2*)&C[(size_t)(rowBase + r0 + lg + 8) * ldc + col] = w1;
    }
}

// ---------------- tf32 MMA flash attention ----------------
// 256 threads (8 warps). Q tile 128 rows, K/V tile 64. Each CTA processes the
// pair (qb = px, qb = 15-px) sequentially -> exactly 34 j-iterations per CTA.
__global__ void __launch_bounds__(256) flash_kernel(
    const float* __restrict__ q, const float* __restrict__ kv,
    float* __restrict__ localOut)
{
    extern __shared__ unsigned sm[];
    unsigned* Qs = sm;                   // [128][68]
    unsigned* Ks = Qs + 128 * 68;        // [64][68]
    unsigned* Vs = Ks + 64 * 68;         // [64][68]
    unsigned* Ps = Vs + 64 * 68;         // [128][68]

    int tid = threadIdx.x;
    int warp = tid >> 5, lane = tid & 31;
    int lg = lane >> 2, lt = lane & 3;
    int bh = blockIdx.y, b = bh >> 3, h = bh & 7;
    int px = blockIdx.x;  // 0..7

    for (int half = 0; half < 2; half++) {
        int qb = half ? (15 - px) : px;
        int i0 = qb * 128;

        // stage Q tile (tf32)
#pragma unroll
        for (int rep = 0; rep < 8; rep++) {
            int r = (tid >> 4) + rep * 16;
            int d4 = (tid & 15) * 4;
            float4 v = *(const float4*)&q[(size_t)(b * Nn + i0 + r) * 512 + h * 64 + d4];
            uint4 u = {f2tf(v.x), f2tf(v.y), f2tf(v.z), f2tf(v.w)};
            *(uint4*)&Qs[r * 68 + d4] = u;
        }

        float o[8][4];
#pragma unroll
        for (int j = 0; j < 8; j++)
#pragma unroll
            for (int qq = 0; qq < 4; qq++) o[j][qq] = 0.f;
        float m_lo = NEG_HUGE, m_hi = NEG_HUGE, l_lo = 0.f, l_hi = 0.f;

        int r0 = warp * 16;
        int row_lo = i0 + r0 + lg;
        int row_hi = row_lo + 8;
        int numJ = 2 * qb + 2;

        for (int jb = 0; jb < numJ; jb++) {
            int j0 = jb * 64;
            __syncthreads();  // all warps done with previous Ks/Vs (and Qs on first iter)
            // stage K,V (tf32)
#pragma unroll
            for (int rep = 0; rep < 4; rep++) {
                int c = (tid >> 4) + rep * 16;
                int d4 = (tid & 15) * 4;
                const float* src = &kv[(size_t)(b * Nn + j0 + c) * 128];
                float4 kk4 = *(const float4*)&src[d4];
                float4 vv4 = *(const float4*)&src[64 + d4];
                uint4 uk = {f2tf(kk4.x), f2tf(kk4.y), f2tf(kk4.z), f2tf(kk4.w)};
                uint4 uv = {f2tf(vv4.x), f2tf(vv4.y), f2tf(vv4.z), f2tf(vv4.w)};
                *(uint4*)&Ks[c * 68 + d4] = uk;
                *(uint4*)&Vs[c * 68 + d4] = uv;
            }
            __syncthreads();

            // S = Q @ K^T  (16 x 64 per warp)
            float sacc[8][4];
#pragma unroll
            for (int j = 0; j < 8; j++)
#pragma unroll
                for (int qq = 0; qq < 4; qq++) sacc[j][qq] = 0.f;
#pragma unroll
            for (int kc = 0; kc < 8; kc++) {
                unsigned a[4];
                a[0] = Qs[(r0 + lg) * 68 + kc * 8 + lt];
                a[1] = Qs[(r0 + lg + 8) * 68 + kc * 8 + lt];
                a[2] = Qs[(r0 + lg) * 68 + kc * 8 + lt + 4];
                a[3] = Qs[(r0 + lg + 8) * 68 + kc * 8 + lt + 4];
#pragma unroll
                for (int jn = 0; jn < 8; jn++) {
                    unsigned bfr[2];
                    bfr[0] = Ks[(jn * 8 + lg) * 68 + kc * 8 + lt];
                    bfr[1] = Ks[(jn * 8 + lg) * 68 + kc * 8 + lt + 4];
                    mma_tf32(sacc[jn], a, bfr);
                }
            }

            // causal mask on the two diagonal-adjacent tiles
            if (jb >= 2 * qb) {
#pragma unroll
                for (int jn = 0; jn < 8; jn++) {
                    int c0 = j0 + jn * 8 + 2 * lt;
                    if (c0 > row_lo) sacc[jn][0] = NEG_HUGE;
                    if (c0 + 1 > row_lo) sacc[jn][1] = NEG_HUGE;
                    if (c0 > row_hi) sacc[jn][2] = NEG_HUGE;
                    if (c0 + 1 > row_hi) sacc[jn][3] = NEG_HUGE;
                }
            }

            // online softmax (rows lo/hi per thread; 4 lanes per row group)
            float mx_lo = NEG_HUGE, mx_hi = NEG_HUGE;
#pragma unroll
            for (int jn = 0; jn < 8; jn++) {
                mx_lo = fmaxf(mx_lo, fmaxf(sacc[jn][0], sacc[jn][1]));
                mx_hi = fmaxf(mx_hi, fmaxf(sacc[jn][2], sacc[jn][3]));
            }
            mx_lo = fmaxf(mx_lo, __shfl_xor_sync(0xffffffffu, mx_lo, 1));
            mx_lo = fmaxf(mx_lo, __shfl_xor_sync(0xffffffffu, mx_lo, 2));
            mx_hi = fmaxf(mx_hi, __shfl_xor_sync(0xffffffffu, mx_hi, 1));
            mx_hi = fmaxf(mx_hi, __shfl_xor_sync(0xffffffffu, mx_hi, 2));
            float nm_lo = fmaxf(m_lo, mx_lo);
            float nm_hi = fmaxf(m_hi, mx_hi);
            float al_lo = __expf((m_lo - nm_lo) * SCALEf);
            float al_hi = __expf((m_hi - nm_hi) * SCALEf);
            m_lo = nm_lo; m_hi = nm_hi;
            float rs_lo = 0.f, rs_hi = 0.f;
#pragma unroll
            for (int jn = 0; jn < 8; jn++) {
                float p0 = __expf((sacc[jn][0] - nm_lo) * SCALEf);
                float p1 = __expf((sacc[jn][1] - nm_lo) * SCALEf);
                float p2 = __expf((sacc[jn][2] - nm_hi) * SCALEf);
                float p3 = __expf((sacc[jn][3] - nm_hi) * SCALEf);
                rs_lo += p0 + p1;
                rs_hi += p2 + p3;
                int cl = jn * 8 + 2 * lt;
                uint2 ulo = {f2tf(p0), f2tf(p1)};
                uint2 uhi = {f2tf(p2), f2tf(p3)};
                *(uint2*)&Ps[(r0 + lg) * 68 + cl] = ulo;
                *(uint2*)&Ps[(r0 + lg + 8) * 68 + cl] = uhi;
                o[jn][0] *= al_lo; o[jn][1] *= al_lo;
                o[jn][2] *= al_hi; o[jn][3] *= al_hi;
            }
            rs_lo += __shfl_xor_sync(0xffffffffu, rs_lo, 1);
            rs_lo += __shfl_xor_sync(0xffffffffu, rs_lo, 2);
            rs_hi += __shfl_xor_sync(0xffffffffu, rs_hi, 1);
            rs_hi += __shfl_xor_sync(0xffffffffu, rs_hi, 2);
            l_lo = l_lo * al_lo + rs_lo;
            l_hi = l_hi * al_hi + rs_hi;

            // O += P @ V  (warp reads only its own P rows -> no extra sync)
#pragma unroll
            for (int kc = 0; kc < 8; kc++) {
                unsigned a[4];
                a[0] = Ps[(r0 + lg) * 68 + kc * 8 + lt];
                a[1] = Ps[(r0 + lg + 8) * 68 + kc * 8 + lt];
                a[2] = Ps[(r0 + lg) * 68 + kc * 8 + lt + 4];
                a[3] = Ps[(r0 + lg + 8) * 68 + kc * 8 + lt + 4];
#pragma unroll
                for (int jn = 0; jn < 8; jn++) {
                    unsigned bfr[2];
                    bfr[0] = Vs[(kc * 8 + lt) * 68 + jn * 8 + lg];
                    bfr[1] = Vs[(kc * 8 + lt + 4) * 68 + jn * 8 + lg];
                    mma_tf32(o[jn], a, bfr);
                }
            }
        }

        float inv_lo = 1.f / l_lo, inv_hi = 1.f / l_hi;
#pragma unroll
        for (int jn = 0; jn < 8; jn++) {
            int col = jn * 8 + 2 * lt;
            float2 w0 = {o[jn][0] * inv_lo, o[jn][1] * inv_lo};
            float2 w1 = {o[jn][2] * inv_hi, o[jn][3] * inv_hi};
            *(float2*)&localOut[((size_t)bh * Nn + row_lo) * 64 + col] = w0;
            *(float2*)&localOut[((size_t)bh * Nn + row_hi) * 64 + col] = w1;
        }
        __syncthreads();  // protect smem before next half re-stages Q
    }
}

// ---------------- memory (KNN) attention + gate combine ----------------
__global__ void mem_attn_kernel(const float* __restrict__ q,
                                const float* __restrict__ memkv,
                                const float* __restrict__ nullk,
                                const float* __restrict__ nullv,
                                const float* __restrict__ gate,
                                const float* __restrict__ localv,
                                float* __restrict__ comb) {
    int gw = blockIdx.x * 8 + (threadIdx.x >> 5);
    int lane = threadIdx.x & 31;
    int b = gw >> 14;
    int rem = gw & 16383;
    int h = rem >> 11;
    int i = rem & 2047;

    const float* qp = &q[(size_t)(b * Nn + i) * 512 + h * 64];
    float q0 = qp[lane], q1 = qp[lane + 32];

    float s = q0 * nullk[lane] + q1 * nullk[lane + 32];
#pragma unroll
    for (int off = 16; off >= 1; off >>= 1) s += __shfl_xor_sync(0xffffffffu, s, off);
    s *= SCALEf;
    float m = s, ls = 1.f;
    float a0 = nullv[lane], a1 = nullv[lane + 32];

    size_t base = (size_t)(b * Hh + h) * Nn + i;
    const unsigned char* mp = &g_mask[base * Kk];
    unsigned mbits = __ballot_sync(0xffffffffu, mp[lane] != 0);
    const float* kvp = &memkv[base * (size_t)(Kk * 2 * DHd)];

    for (int kk = 0; kk < Kk; kk++) {
        if (!((mbits >> kk) & 1u)) continue;
        const float* kp = kvp + (size_t)kk * 128;
        float ss = q0 * kp[lane] + q1 * kp[lane + 32];
#pragma unroll
        for (int off = 16; off >= 1; off >>= 1) ss += __shfl_xor_sync(0xffffffffu, ss, off);
        ss *= SCALEf;
        float nm = fmaxf(m, ss);
        float al = __expf(m - nm);
        float p = __expf(ss - nm);
        m = nm;
        ls = ls * al + p;
        a0 = a0 * al + p * kp[64 + lane];
        a1 = a1 * al + p * kp[96 + lane];
    }
    float inv = 1.f / ls;
    float mem0 = a0 * inv, mem1 = a1 * inv;

    float g = 1.f / (1.f + __expf(-gate[h]));
    const float* lp = &localv[base * DHd];
    float* cp = &comb[(size_t)(b * Nn + i) * 512 + h * 64];
    cp[lane]      = lp[lane]      * g + mem0 * (1.f - g);
    cp[lane + 32] = lp[lane + 32] * g + mem1 * (1.f - g);
}

// ---------------- launch ----------------
extern "C" void kernel_launch(void* const* d_in, const int* in_sizes, int n_in,
                              void* d_out, int out_size) {
    const float* x      = (const float*)d_in[0];
    const float* mem_kv = (const float*)d_in[1];
    const void*  m_mask = d_in[2];
    const float* Wq     = (const float*)d_in[3];
    const float* Wkv    = (const float*)d_in[4];
    const float* Wo     = (const float*)d_in[5];
    const float* bo     = (const float*)d_in[6];
    const float* null_k = (const float*)d_in[7];
    const float* null_v = (const float*)d_in[8];
    const float* gate   = (const float*)d_in[9];
    float* out = (float*)d_out;

    float* q_buf;     cudaGetSymbolAddress((void**)&q_buf, g_q);
    float* kv_buf;    cudaGetSymbolAddress((void**)&kv_buf, g_kv);
    float* local_buf; cudaGetSymbolAddress((void**)&local_buf, g_local);
    float* comb_buf;  cudaGetSymbolAddress((void**)&comb_buf, g_comb);

    const int FLASH_SMEM = (128 + 64 + 64 + 128) * 68 * 4;  // 104448 B
    cudaFuncSetAttribute(flash_kernel, cudaFuncAttributeMaxDynamicSharedMemorySize,
                         FLASH_SMEM);

    detect_mask_kernel<<<1, 256>>>((const unsigned int*)m_mask);
    expand_mask_kernel<<<(Bb * Hh * Nn * Kk + 255) / 256, 256>>>(m_mask,
                                                                 Bb * Hh * Nn * Kk);

    // fused q + kv projection: n-tiles 0..7 -> Wq/g_q, 8..9 -> Wkv/g_kv
    gemm_kernel<<<dim3(10, (Bb * Nn) / 128), 256>>>(
        x, Wq, q_buf, 512, 512, Wkv, kv_buf, 128, 128, 8, nullptr, 512);

    // local causal flash attention (paired qb -> uniform 34 iters per CTA)
    flash_kernel<<<dim3(8, Bb * Hh), 256, FLASH_SMEM>>>(q_buf, kv_buf, local_buf);

    // memory attention + gate combine
    mem_attn_kernel<<<(Bb * Hh * Nn) / 8, 256>>>(q_buf, mem_kv, null_k, null_v,
                                                 gate, local_buf, comb_buf);

    // output projection with bias (single B, nb1=0 -> all blocks use (B2,C2))
    gemm_kernel<<<dim3(8, (Bb * Nn) / 128), 256>>>(
        comb_buf, Wo, out, 512, 512, Wo, out, 512, 512, 0, bo, 512);
}

// round 4
// speedup vs baseline: 3.9242x; 1.5261x over previous
#include <cuda_runtime.h>
#include <cuda_fp16.h>
#include <cstdint>

#define Bb 2
#define Nn 2048
#define Hh 8
#define DHd 64
#define Kk 32
#define SCALEf 0.125f
#define NEG_HUGE (-3.402823466e+38f)

// ---------------- mma / ldmatrix helpers ----------------
__device__ __forceinline__ void ldsm4(uint32_t& r0, uint32_t& r1, uint32_t& r2,
                                      uint32_t& r3, uint32_t addr) {
    asm volatile("ldmatrix.sync.aligned.m8n8.x4.shared.b16 {%0,%1,%2,%3}, [%4];"
                 : "=r"(r0), "=r"(r1), "=r"(r2), "=r"(r3) : "r"(addr));
}
__device__ __forceinline__ void ldsm4t(uint32_t& r0, uint32_t& r1, uint32_t& r2,
                                       uint32_t& r3, uint32_t addr) {
    asm volatile("ldmatrix.sync.aligned.m8n8.x4.trans.shared.b16 {%0,%1,%2,%3}, [%4];"
                 : "=r"(r0), "=r"(r1), "=r"(r2), "=r"(r3) : "r"(addr));
}
__device__ __forceinline__ void mma_f16(float* d, const uint32_t* a,
                                        uint32_t b0, uint32_t b1) {
    asm volatile(
        "mma.sync.aligned.m16n8k16.row.col.f32.f16.f16.f32 "
        "{%0,%1,%2,%3}, {%4,%5,%6,%7}, {%8,%9}, {%0,%1,%2,%3};"
        : "+f"(d[0]), "+f"(d[1]), "+f"(d[2]), "+f"(d[3])
        : "r"(a[0]), "r"(a[1]), "r"(a[2]), "r"(a[3]), "r"(b0), "r"(b1));
}
__device__ __forceinline__ uint32_t h2u(float x, float y) {
    __half2 h = __floats2half2_rn(x, y);
    return *(uint32_t*)&h;
}

// ---------------- scratch ----------------
__device__ __half g_q[Bb * Nn * (Hh * DHd)];
__device__ __half g_kv[Bb * Nn * (2 * DHd)];
__device__ float g_local[Bb * Hh * Nn * DHd];
__device__ float g_comb[Bb * Nn * (Hh * DHd)];
__device__ unsigned char g_mask[Bb * Hh * Nn * Kk];
__device__ int g_mask_mode;

// ---------------- mask dtype detection / expansion ----------------
__global__ void detect_mask_kernel(const unsigned int* __restrict__ raw) {
    __shared__ int cf, ch;
    if (threadIdx.x == 0) { cf = 0; ch = 0; }
    __syncthreads();
    int lf = 0, lh = 0;
    for (int idx = threadIdx.x; idx < 4096; idx += 256) {
        unsigned w = raw[idx];
        if (w == 0x3f800000u) lf++;
        if (w & 0xFFFFFF00u) lh++;
    }
    atomicAdd(&cf, lf);
    atomicAdd(&ch, lh);
    __syncthreads();
    if (threadIdx.x == 0) {
        int mode;
        if (cf > 64) mode = 2;
        else if (ch > 64) mode = 0;
        else mode = 1;
        g_mask_mode = mode;
    }
}

__global__ void expand_mask_kernel(const void* __restrict__ raw, int n) {
    int idx = blockIdx.x * blockDim.x + threadIdx.x;
    if (idx >= n) return;
    int mode = g_mask_mode;
    unsigned char v;
    if (mode == 0)      v = ((const unsigned char*)raw)[idx] != 0;
    else if (mode == 1) v = ((const int*)raw)[idx] != 0;
    else                v = (((const float*)raw)[idx] != 0.0f);
    g_mask[idx] = v;
}

// ---------------- fp16 MMA GEMM: tile 128x64, BK=32, 256 threads (8 warps) ----------------
template <bool OUT_HALF>
__global__ void __launch_bounds__(256) gemm_kernel(
    const float* __restrict__ A,
    const float* __restrict__ B1, void* __restrict__ C1, int ldb1, int ldc1,
    const float* __restrict__ B2, void* __restrict__ C2, int ldb2, int ldc2,
    int nb1, const float* __restrict__ bias, int Kd)
{
    __shared__ __half As[128 * 40];  // [r][k], stride 40 halfs
    __shared__ __half Bs[32 * 72];   // [k][n], stride 72 halfs
    int tid = threadIdx.x;
    int warp = tid >> 5, lane = tid & 31;
    int lg = lane >> 2, lt = lane & 3;
    int rowBase = blockIdx.y * 128;
    const float* Bm; void* C; int ldb, ldc, colBase;
    bool hasBias;
    if ((int)blockIdx.x < nb1) {
        Bm = B1; C = C1; ldb = ldb1; ldc = ldc1; colBase = blockIdx.x * 64;
        hasBias = false;
    } else {
        Bm = B2; C = C2; ldb = ldb2; ldc = ldc2; colBase = (blockIdx.x - nb1) * 64;
        hasBias = (bias != nullptr);
    }

    uint32_t asb = (uint32_t)__cvta_generic_to_shared(As);
    uint32_t bsb = (uint32_t)__cvta_generic_to_shared(Bs);
    int a_row = (lane & 7) + (lane & 8);      // row offset for A-style frags
    int a_cb = (lane & 16) >> 1;              // col offset 0/8

    float acc[8][4];
#pragma unroll
    for (int j = 0; j < 8; j++)
#pragma unroll
        for (int q = 0; q < 4; q++) acc[j][q] = 0.f;

    int r0 = warp * 16;

    for (int k0 = 0; k0 < Kd; k0 += 32) {
        // stage A 128x32 -> fp16
#pragma unroll
        for (int rep = 0; rep < 4; rep++) {
            int r = (tid >> 3) + rep * 32;
            int kq = (tid & 7) * 4;
            float4 v = *(const float4*)&A[(size_t)(rowBase + r) * Kd + k0 + kq];
            uint2 u = {h2u(v.x, v.y), h2u(v.z, v.w)};
            *(uint2*)&As[r * 40 + kq] = u;
        }
        // stage B 32x64 -> fp16
#pragma unroll
        for (int rep = 0; rep < 2; rep++) {
            int kk = (tid >> 4) + rep * 16;
            int c4 = (tid & 15) * 4;
            float4 v = *(const float4*)&Bm[(size_t)(k0 + kk) * ldb + colBase + c4];
            uint2 u = {h2u(v.x, v.y), h2u(v.z, v.w)};
            *(uint2*)&Bs[kk * 72 + c4] = u;
        }
        __syncthreads();
#pragma unroll
        for (int kc = 0; kc < 2; kc++) {
            uint32_t a[4];
            ldsm4(a[0], a[1], a[2], a[3],
                  asb + ((r0 + a_row) * 40 + kc * 16 + a_cb) * 2);
#pragma unroll
            for (int jn2 = 0; jn2 < 4; jn2++) {
                uint32_t b0, b1, b2, b3;
                ldsm4t(b0, b1, b2, b3,
                       bsb + ((kc * 16 + a_row) * 72 + jn2 * 16 + a_cb) * 2);
                mma_f16(acc[2 * jn2], a, b0, b1);
                mma_f16(acc[2 * jn2 + 1], a, b2, b3);
            }
        }
        __syncthreads();
    }

#pragma unroll
    for (int jn = 0; jn < 8; jn++) {
        int col = colBase + jn * 8 + 2 * lt;
        float b0 = 0.f, b1 = 0.f;
        if (hasBias) { b0 = bias[col]; b1 = bias[col + 1]; }
        size_t off0 = (size_t)(rowBase + r0 + lg) * ldc + col;
        size_t off1 = (size_t)(rowBase + r0 + lg + 8) * ldc + col;
        if (OUT_HALF) {
            *(__half2*)&((__half*)C)[off0] =
                __floats2half2_rn(acc[jn][0] + b0, acc[jn][1] + b1);
            *(__half2*)&((__half*)C)[off1] =
                __floats2half2_rn(acc[jn][2] + b0, acc[jn][3] + b1);
        } else {
            float2 w0 = {acc[jn][0] + b0, acc[jn][1] + b1};
            float2 w1 = {acc[jn][2] + b0, acc[jn][3] + b1};
            *(float2*)&((float*)C)[off0] = w0;
            *(float2*)&((float*)C)[off1] = w1;
        }
    }
}

// ---------------- fp16 MMA flash attention ----------------
// 256 threads / 8 warps, Q tile 128, K/V tile 64. CTA handles pair (px, 15-px)
// -> uniform 34 j-iterations. P stays in registers (accum -> A-frag convert).
__global__ void __launch_bounds__(256) flash_kernel(
    const __half* __restrict__ q, const __half* __restrict__ kv,
    float* __restrict__ localOut)
{
    __shared__ __half Qs[128 * 72];
    __shared__ __half Ks[64 * 72];
    __shared__ __half Vs[64 * 72];

    int tid = threadIdx.x;
    int warp = tid >> 5, lane = tid & 31;
    int lg = lane >> 2, lt = lane & 3;
    int bh = blockIdx.y, b = bh >> 3, h = bh & 7;
    int px = blockIdx.x;  // 0..7

    uint32_t qsb = (uint32_t)__cvta_generic_to_shared(Qs);
    uint32_t ksb = (uint32_t)__cvta_generic_to_shared(Ks);
    uint32_t vsb = (uint32_t)__cvta_generic_to_shared(Vs);
    int a_row = (lane & 7) + (lane & 8);       // A/V-style: row gets bit3, col gets bit4
    int a_cb = (lane & 16) >> 1;
    int k_row = (lane & 7) + ((lane & 16) >> 1);  // K-style: row gets bit4, col gets bit3
    int k_cb = (lane & 8);

    int r0 = warp * 16;

    for (int half_i = 0; half_i < 2; half_i++) {
        int qb = half_i ? (15 - px) : px;
        int i0 = qb * 128;

        // stage Q tile (fp16, 8 halfs per uint4)
#pragma unroll
        for (int rep = 0; rep < 4; rep++) {
            int idx = tid + rep * 256;
            int r = idx >> 3;
            int c8 = (idx & 7) * 8;
            *(uint4*)&Qs[r * 72 + c8] =
                *(const uint4*)&q[(size_t)(b * Nn + i0 + r) * 512 + h * 64 + c8];
        }
        __syncthreads();

        // hoisted Q fragments
        uint32_t qa[4][4];
#pragma unroll
        for (int kc = 0; kc < 4; kc++)
            ldsm4(qa[kc][0], qa[kc][1], qa[kc][2], qa[kc][3],
                  qsb + ((r0 + a_row) * 72 + kc * 16 + a_cb) * 2);

        float o[8][4];
#pragma unroll
        for (int j = 0; j < 8; j++)
#pragma unroll
            for (int qq = 0; qq < 4; qq++) o[j][qq] = 0.f;
        float m_lo = NEG_HUGE, m_hi = NEG_HUGE, l_lo = 0.f, l_hi = 0.f;

        int row_lo = i0 + r0 + lg;
        int row_hi = row_lo + 8;
        int numJ = 2 * qb + 2;

        for (int jb = 0; jb < numJ; jb++) {
            int j0 = jb * 64;
            __syncthreads();
            // stage K,V (64 rows x 128 halfs of kv)
#pragma unroll
            for (int rep = 0; rep < 4; rep++) {
                int idx = tid + rep * 256;
                int c = idx >> 4;
                int q8 = (idx & 15) * 8;
                uint4 v = *(const uint4*)&kv[(size_t)(b * Nn + j0 + c) * 128 + q8];
                if (q8 < 64) *(uint4*)&Ks[c * 72 + q8] = v;
                else         *(uint4*)&Vs[c * 72 + q8 - 64] = v;
            }
            __syncthreads();

            // S = Q @ K^T  (16x64 per warp)
            float sacc[8][4];
#pragma unroll
            for (int j = 0; j < 8; j++)
#pragma unroll
                for (int qq = 0; qq < 4; qq++) sacc[j][qq] = 0.f;
#pragma unroll
            for (int kc = 0; kc < 4; kc++) {
#pragma unroll
                for (int jn2 = 0; jn2 < 4; jn2++) {
                    uint32_t b0, b1, b2, b3;
                    ldsm4(b0, b1, b2, b3,
                          ksb + ((jn2 * 16 + k_row) * 72 + kc * 16 + k_cb) * 2);
                    mma_f16(sacc[2 * jn2], qa[kc], b0, b1);
                    mma_f16(sacc[2 * jn2 + 1], qa[kc], b2, b3);
                }
            }

            // causal mask on diagonal-adjacent tiles
            if (jb >= 2 * qb) {
#pragma unroll
                for (int jn = 0; jn < 8; jn++) {
                    int c0 = j0 + jn * 8 + 2 * lt;
                    if (c0 > row_lo) sacc[jn][0] = NEG_HUGE;
                    if (c0 + 1 > row_lo) sacc[jn][1] = NEG_HUGE;
                    if (c0 > row_hi) sacc[jn][2] = NEG_HUGE;
                    if (c0 + 1 > row_hi) sacc[jn][3] = NEG_HUGE;
                }
            }

            // online softmax
            float mx_lo = NEG_HUGE, mx_hi = NEG_HUGE;
#pragma unroll
            for (int jn = 0; jn < 8; jn++) {
                mx_lo = fmaxf(mx_lo, fmaxf(sacc[jn][0], sacc[jn][1]));
                mx_hi = fmaxf(mx_hi, fmaxf(sacc[jn][2], sacc[jn][3]));
            }
            mx_lo = fmaxf(mx_lo, __shfl_xor_sync(0xffffffffu, mx_lo, 1));
            mx_lo = fmaxf(mx_lo, __shfl_xor_sync(0xffffffffu, mx_lo, 2));
            mx_hi = fmaxf(mx_hi, __shfl_xor_sync(0xffffffffu, mx_hi, 1));
            mx_hi = fmaxf(mx_hi, __shfl_xor_sync(0xffffffffu, mx_hi, 2));
            float nm_lo = fmaxf(m_lo, mx_lo);
            float nm_hi = fmaxf(m_hi, mx_hi);
            float al_lo = __expf((m_lo - nm_lo) * SCALEf);
            float al_hi = __expf((m_hi - nm_hi) * SCALEf);
            m_lo = nm_lo; m_hi = nm_hi;

            // P -> register-resident fp16 A-fragments
            uint32_t pa[4][4];
            float rs_lo = 0.f, rs_hi = 0.f;
#pragma unroll
            for (int jn = 0; jn < 8; jn++) {
                float p0 = __expf((sacc[jn][0] - nm_lo) * SCALEf);
                float p1 = __expf((sacc[jn][1] - nm_lo) * SCALEf);
                float p2 = __expf((sacc[jn][2] - nm_hi) * SCALEf);
                float p3 = __expf((sacc[jn][3] - nm_hi) * SCALEf);
                rs_lo += p0 + p1;
                rs_hi += p2 + p3;
                int kc = jn >> 1;
                int hi = (jn & 1) ? 2 : 0;
                pa[kc][hi] = h2u(p0, p1);
                pa[kc][hi + 1] = h2u(p2, p3);
                o[jn][0] *= al_lo; o[jn][1] *= al_lo;
                o[jn][2] *= al_hi; o[jn][3] *= al_hi;
            }
            rs_lo += __shfl_xor_sync(0xffffffffu, rs_lo, 1);
            rs_lo += __shfl_xor_sync(0xffffffffu, rs_lo, 2);
            rs_hi += __shfl_xor_sync(0xffffffffu, rs_hi, 1);
            rs_hi += __shfl_xor_sync(0xffffffffu, rs_hi, 2);
            l_lo = l_lo * al_lo + rs_lo;
            l_hi = l_hi * al_hi + rs_hi;

            // O += P @ V
#pragma unroll
            for (int kc = 0; kc < 4; kc++) {
#pragma unroll
                for (int dn2 = 0; dn2 < 4; dn2++) {
                    uint32_t b0, b1, b2, b3;
                    ldsm4t(b0, b1, b2, b3,
                           vsb + ((kc * 16 + a_row) * 72 + dn2 * 16 + a_cb) * 2);
                    mma_f16(o[2 * dn2], pa[kc], b0, b1);
                    mma_f16(o[2 * dn2 + 1], pa[kc], b2, b3);
                }
            }
        }

        float inv_lo = 1.f / l_lo, inv_hi = 1.f / l_hi;
#pragma unroll
        for (int jn = 0; jn < 8; jn++) {
            int col = jn * 8 + 2 * lt;
            float2 w0 = {o[jn][0] * inv_lo, o[jn][1] * inv_lo};
            float2 w1 = {o[jn][2] * inv_hi, o[jn][3] * inv_hi};
            *(float2*)&localOut[((size_t)bh * Nn + row_lo) * 64 + col] = w0;
            *(float2*)&localOut[((size_t)bh * Nn + row_hi) * 64 + col] = w1;
        }
        __syncthreads();  // protect smem before next half re-stages Q
    }
}

// ---------------- memory (KNN) attention + gate combine ----------------
__global__ void mem_attn_kernel(const __half* __restrict__ q,
                                const float* __restrict__ memkv,
                                const float* __restrict__ nullk,
                                const float* __restrict__ nullv,
                                const float* __restrict__ gate,
                                const float* __restrict__ localv,
                                float* __restrict__ comb) {
    int gw = blockIdx.x * 8 + (threadIdx.x >> 5);
    int lane = threadIdx.x & 31;
    int b = gw >> 14;
    int rem = gw & 16383;
    int h = rem >> 11;
    int i = rem & 2047;

    const __half* qp = &q[(size_t)(b * Nn + i) * 512 + h * 64];
    float q0 = __half2float(qp[lane]), q1 = __half2float(qp[lane + 32]);

    float s = q0 * nullk[lane] + q1 * nullk[lane + 32];
#pragma unroll
    for (int off = 16; off >= 1; off >>= 1) s += __shfl_xor_sync(0xffffffffu, s, off);
    s *= SCALEf;
    float m = s, ls = 1.f;
    float a0 = nullv[lane], a1 = nullv[lane + 32];

    size_t base = (size_t)(b * Hh + h) * Nn + i;
    const unsigned char* mp = &g_mask[base * Kk];
    unsigned mbits = __ballot_sync(0xffffffffu, mp[lane] != 0);
    const float* kvp = &memkv[base * (size_t)(Kk * 2 * DHd)];

    for (int kk = 0; kk < Kk; kk++) {
        if (!((mbits >> kk) & 1u)) continue;
        const float* kp = kvp + (size_t)kk * 128;
        float ss = q0 * __ldcs(&kp[lane]) + q1 * __ldcs(&kp[lane + 32]);
#pragma unroll
        for (int off = 16; off >= 1; off >>= 1) ss += __shfl_xor_sync(0xffffffffu, ss, off);
        ss *= SCALEf;
        float nm = fmaxf(m, ss);
        float al = __expf(m - nm);
        float p = __expf(ss - nm);
        m = nm;
        ls = ls * al + p;
        a0 = a0 * al + p * __ldcs(&kp[64 + lane]);
        a1 = a1 * al + p * __ldcs(&kp[96 + lane]);
    }
    float inv = 1.f / ls;
    float mem0 = a0 * inv, mem1 = a1 * inv;

    float g = 1.f / (1.f + __expf(-gate[h]));
    const float* lp = &localv[base * DHd];
    float* cp = &comb[(size_t)(b * Nn + i) * 512 + h * 64];
    cp[lane]      = lp[lane]      * g + mem0 * (1.f - g);
    cp[lane + 32] = lp[lane + 32] * g + mem1 * (1.f - g);
}

// ---------------- launch ----------------
extern "C" void kernel_launch(void* const* d_in, const int* in_sizes, int n_in,
                              void* d_out, int out_size) {
    const float* x      = (const float*)d_in[0];
    const float* mem_kv = (const float*)d_in[1];
    const void*  m_mask = d_in[2];
    const float* Wq     = (const float*)d_in[3];
    const float* Wkv    = (const float*)d_in[4];
    const float* Wo     = (const float*)d_in[5];
    const float* bo     = (const float*)d_in[6];
    const float* null_k = (const float*)d_in[7];
    const float* null_v = (const float*)d_in[8];
    const float* gate   = (const float*)d_in[9];
    float* out = (float*)d_out;

    __half* q_buf;    cudaGetSymbolAddress((void**)&q_buf, g_q);
    __half* kv_buf;   cudaGetSymbolAddress((void**)&kv_buf, g_kv);
    float* local_buf; cudaGetSymbolAddress((void**)&local_buf, g_local);
    float* comb_buf;  cudaGetSymbolAddress((void**)&comb_buf, g_comb);

    detect_mask_kernel<<<1, 256>>>((const unsigned int*)m_mask);
    expand_mask_kernel<<<(Bb * Hh * Nn * Kk + 255) / 256, 256>>>(m_mask,
                                                                 Bb * Hh * Nn * Kk);

    // fused q + kv projection (fp16 outputs): tiles 0..7 -> Wq/g_q, 8..9 -> Wkv/g_kv
    gemm_kernel<true><<<dim3(10, (Bb * Nn) / 128), 256>>>(
        x, Wq, q_buf, 512, 512, Wkv, kv_buf, 128, 128, 8, nullptr, 512);

    // local causal flash attention
    flash_kernel<<<dim3(8, Bb * Hh), 256>>>(q_buf, kv_buf, local_buf);

    // memory attention + gate combine
    mem_attn_kernel<<<(Bb * Hh * Nn) / 8, 256>>>(q_buf, mem_kv, null_k, null_v,
                                                 gate, local_buf, comb_buf);

    // output projection with bias (float output)
    gemm_kernel<false><<<dim3(8, (Bb * Nn) / 128), 256>>>(
        comb_buf, Wo, out, 512, 512, Wo, out, 512, 512, 0, bo, 512);
}